// round 14
// baseline (speedup 1.0000x reference)
#include <cuda_runtime.h>
#include <cstdint>

// ---------------------------------------------------------------------------
// LinearAttention: B=128, N=196, C=768, h=12, e=64, num_frames=16
//   b = 8, S = 3136, M = 25088 tokens.  (B,N)->(b,S) reshape is row-identity.
//
// Stage 1: qkv = x @ W_qkv^T          -> tf32 mma.sync GEMM, relu+scatter epi
// Stage 2: kv[b,h,e,d], k_sum[b,h,e]  -> fp32 SIMT split-K (small: 2.5 GF)
// Stage 3: out = (q.kv)/(q.k_sum+eps) -> fp32 SIMT
// Stage 4: final = out @ W_proj^T + b -> tf32 mma.sync GEMM, bias epi
//
// GEMM mainloop is a 2-stage cp.async pipeline: global->smem copy of K-chunk
// c+1 overlaps the MMAs of chunk c. Smem holds raw f32; cvt.rna.tf32 happens
// at fragment load (alu pipe has headroom; tensor pipe was 47% idle waiting
// on the serialized loads).
// ---------------------------------------------------------------------------

#define MTOK   25088
#define CDIM   768
#define SLEN   3136
#define NBH    96
#define KSPLIT 7
#define SCHUNK 448

__device__ float g_q  [(size_t)MTOK * CDIM];
__device__ float g_k  [(size_t)MTOK * CDIM];
__device__ float g_v  [(size_t)MTOK * CDIM];
__device__ float g_att[(size_t)MTOK * CDIM];
__device__ float g_kvp [NBH * KSPLIT * 64 * 64];
__device__ float g_ksp [NBH * KSPLIT * 64];

__device__ __forceinline__ uint32_t f32_to_tf32(float f) {
    uint32_t r;
    asm("cvt.rna.tf32.f32 %0, %1;" : "=r"(r) : "f"(f));
    return r;
}
__device__ __forceinline__ uint32_t smem_u32(const void* p) {
    uint32_t a;
    asm("{ .reg .u64 t; cvta.to.shared.u64 t, %1; cvt.u32.u64 %0, t; }"
        : "=r"(a) : "l"(p));
    return a;
}
__device__ __forceinline__ void cp_async16(uint32_t dst, const void* src) {
    asm volatile("cp.async.cg.shared.global [%0], [%1], 16;"
                 :: "r"(dst), "l"(src));
}
__device__ __forceinline__ void cp_commit() {
    asm volatile("cp.async.commit_group;" ::: "memory");
}
__device__ __forceinline__ void cp_wait1() {
    asm volatile("cp.async.wait_group 1;" ::: "memory");
}
__device__ __forceinline__ void cp_wait0() {
    asm volatile("cp.async.wait_group 0;" ::: "memory");
}

// D += A(16x8,row) x B(8x8,col) in tf32, f32 accum.
__device__ __forceinline__ void mma_tf32(float c[4],
                                         const uint32_t a[4],
                                         const uint32_t b[2])
{
    asm volatile(
        "mma.sync.aligned.m16n8k8.row.col.f32.tf32.tf32.f32 "
        "{%0,%1,%2,%3}, {%4,%5,%6,%7}, {%8,%9}, {%0,%1,%2,%3};\n"
        : "+f"(c[0]), "+f"(c[1]), "+f"(c[2]), "+f"(c[3])
        : "r"(a[0]), "r"(a[1]), "r"(a[2]), "r"(a[3]),
          "r"(b[0]), "r"(b[1]));
}

// ---------------------------------------------------------------------------
// tf32 GEMM: C[128 x 128] tile of A(MxK,row) @ Bt(NxK,row)^T, K = 768.
// 256 thr = 8 warps (2 m x 4 n); warp = 64x32 via 4x4 m16n8k8 frags.
// 2-stage cp.async pipeline, KCHUNK=16, smem pitch 20 words
// (banks 20g+tig distinct mod 32 -> conflict-free fragment LDS).
// mode 0: qkv epilogue (relu on q,k; scatter to g_q/g_k/g_v)
// mode 1: proj epilogue (+bias -> out)
// ---------------------------------------------------------------------------
#define KCHUNK 16
#define NCHUNK (CDIM / KCHUNK)   // 48
#define SPAD   20

__global__ __launch_bounds__(256, 2)
void mma_gemm_kernel(const float* __restrict__ A, const float* __restrict__ Bt,
                     const float* __restrict__ bias, float* __restrict__ out,
                     int mode)
{
    __shared__ float As[2][128][SPAD];   // [stage][m][k], 16 valid k cols
    __shared__ float Bs[2][128][SPAD];   // [stage][n][k]

    const int t     = threadIdx.x;
    const int mBase = blockIdx.x * 128;
    const int nBase = blockIdx.y * 128;

    const float* Ap = A ? A : g_att;     // proj reads the attention output

    const int wid  = t >> 5;
    const int lane = t & 31;
    const int g    = lane >> 2;          // group id 0..7
    const int tig  = lane & 3;           // thread-in-group
    const int wm   = (wid >> 2) * 64;    // warp m offset
    const int wn   = (wid & 3) * 32;     // warp n offset

    // fill mapping: 512 float4 per matrix per chunk; 2 per thread per matrix
    const int fr = t >> 2;               // row (+0 / +64)
    const int fk = (t & 3) * 4;          // k word offset

    const float* ArowP = Ap + (size_t)(mBase + fr) * CDIM + fk;
    const float* BrowP = Bt + (size_t)(nBase + fr) * CDIM + fk;

    uint32_t sA[2][2], sB[2][2];
#pragma unroll
    for (int st = 0; st < 2; st++)
#pragma unroll
        for (int i = 0; i < 2; i++) {
            sA[st][i] = smem_u32(&As[st][fr + i * 64][fk]);
            sB[st][i] = smem_u32(&Bs[st][fr + i * 64][fk]);
        }

    float acc[4][4][4];
#pragma unroll
    for (int i = 0; i < 4; i++)
#pragma unroll
        for (int j = 0; j < 4; j++)
#pragma unroll
            for (int r = 0; r < 4; r++) acc[i][j][r] = 0.f;

    // prologue: issue chunk 0 into stage 0
#pragma unroll
    for (int i = 0; i < 2; i++) {
        cp_async16(sA[0][i], ArowP + (size_t)i * 64 * CDIM);
        cp_async16(sB[0][i], BrowP + (size_t)i * 64 * CDIM);
    }
    cp_commit();

    for (int c = 0; c < NCHUNK; ++c) {
        const int buf = c & 1;
        if (c + 1 < NCHUNK) {
            const int kOff = (c + 1) * KCHUNK;
            const int nb   = buf ^ 1;
#pragma unroll
            for (int i = 0; i < 2; i++) {
                cp_async16(sA[nb][i], ArowP + (size_t)i * 64 * CDIM + kOff);
                cp_async16(sB[nb][i], BrowP + (size_t)i * 64 * CDIM + kOff);
            }
            cp_commit();
            cp_wait1();                  // chunk c complete (1 group pending)
        } else {
            cp_wait0();
        }
        __syncthreads();

#pragma unroll
        for (int ks = 0; ks < 2; ks++) {
            const int k0 = ks * 8;
            uint32_t afr[4][4];
#pragma unroll
            for (int mt = 0; mt < 4; mt++) {
                const int r0 = wm + mt * 16 + g;
                afr[mt][0] = f32_to_tf32(As[buf][r0]    [k0 + tig]);
                afr[mt][1] = f32_to_tf32(As[buf][r0 + 8][k0 + tig]);
                afr[mt][2] = f32_to_tf32(As[buf][r0]    [k0 + tig + 4]);
                afr[mt][3] = f32_to_tf32(As[buf][r0 + 8][k0 + tig + 4]);
            }
            uint32_t bfr[4][2];
#pragma unroll
            for (int nt = 0; nt < 4; nt++) {
                const int rn = wn + nt * 8 + g;
                bfr[nt][0] = f32_to_tf32(Bs[buf][rn][k0 + tig]);
                bfr[nt][1] = f32_to_tf32(Bs[buf][rn][k0 + tig + 4]);
            }
#pragma unroll
            for (int mt = 0; mt < 4; mt++)
#pragma unroll
                for (int nt = 0; nt < 4; nt++)
                    mma_tf32(acc[mt][nt], afr[mt], bfr[nt]);
        }
        __syncthreads();                 // all reads done before refill
    }

    // Epilogue. 128-wide n-tiles never straddle the 768 boundary (768%128==0).
    if (mode == 0) {
        const int which = nBase / CDIM;            // 0=q 1=k 2=v
        float* dst = (which == 0) ? g_q : (which == 1) ? g_k : g_v;
        const int lcolBase = nBase - which * CDIM;
        const bool doRelu = (which < 2);
#pragma unroll
        for (int mt = 0; mt < 4; mt++) {
#pragma unroll
            for (int nt = 0; nt < 4; nt++) {
                const int row0 = mBase + wm + mt * 16 + g;
                const int col  = lcolBase + wn + nt * 8 + tig * 2;
                float2 v01 = { acc[mt][nt][0], acc[mt][nt][1] };
                float2 v23 = { acc[mt][nt][2], acc[mt][nt][3] };
                if (doRelu) {
                    v01.x = fmaxf(v01.x, 0.f); v01.y = fmaxf(v01.y, 0.f);
                    v23.x = fmaxf(v23.x, 0.f); v23.y = fmaxf(v23.y, 0.f);
                }
                *(float2*)&dst[(size_t)row0 * CDIM + col]       = v01;
                *(float2*)&dst[(size_t)(row0 + 8) * CDIM + col] = v23;
            }
        }
    } else {
#pragma unroll
        for (int mt = 0; mt < 4; mt++) {
#pragma unroll
            for (int nt = 0; nt < 4; nt++) {
                const int row0 = mBase + wm + mt * 16 + g;
                const int col  = nBase + wn + nt * 8 + tig * 2;
                const float2 b2 = *(const float2*)&bias[col];
                float2 v01 = { acc[mt][nt][0] + b2.x, acc[mt][nt][1] + b2.y };
                float2 v23 = { acc[mt][nt][2] + b2.x, acc[mt][nt][3] + b2.y };
                *(float2*)&out[(size_t)row0 * CDIM + col]       = v01;
                *(float2*)&out[(size_t)(row0 + 8) * CDIM + col] = v23;
            }
        }
    }
}

// ---------------------------------------------------------------------------
// Stage 2: per-(b,h) 64x64 kv = K^T V and k_sum, split-K over s (7 partials).
// ---------------------------------------------------------------------------
__global__ __launch_bounds__(256)
void kv_partial_kernel()
{
    __shared__ float ks[16][64];
    __shared__ float vs[16][64];

    const int bh    = blockIdx.x;
    const int b     = bh / 12;
    const int h     = bh - b * 12;
    const int split = blockIdx.y;
    const int s0    = split * SCHUNK;

    const int t  = threadIdx.x;
    const int te = (t & 15) << 2;
    const int td = (t >> 4) << 2;

    const float* kbase = g_k + (size_t)b * SLEN * CDIM + h * 64;
    const float* vbase = g_v + (size_t)b * SLEN * CDIM + h * 64;

    const int lrow = t >> 4;
    const int lc4  = t & 15;

    float acc[4][4];
#pragma unroll
    for (int i = 0; i < 4; i++)
#pragma unroll
        for (int j = 0; j < 4; j++) acc[i][j] = 0.f;
    float ksum_acc = 0.f;

    for (int c = 0; c < SCHUNK / 16; ++c) {
        const int s = s0 + c * 16;
        __syncthreads();
        ((float4*)ks[lrow])[lc4] =
            *(const float4*)&kbase[(size_t)(s + lrow) * CDIM + lc4 * 4];
        ((float4*)vs[lrow])[lc4] =
            *(const float4*)&vbase[(size_t)(s + lrow) * CDIM + lc4 * 4];
        __syncthreads();

        if (t < 64) {
#pragma unroll
            for (int ss = 0; ss < 16; ss++) ksum_acc += ks[ss][t];
        }
#pragma unroll
        for (int ss = 0; ss < 16; ss++) {
            float4 k4 = ((const float4*)ks[ss])[t & 15];
            float4 v4 = ((const float4*)vs[ss])[t >> 4];
            float kv_[4] = {k4.x, k4.y, k4.z, k4.w};
            float vv_[4] = {v4.x, v4.y, v4.z, v4.w};
#pragma unroll
            for (int i = 0; i < 4; i++)
#pragma unroll
                for (int j = 0; j < 4; j++) acc[i][j] += kv_[i] * vv_[j];
        }
    }

    float* kvdst = g_kvp + ((size_t)bh * KSPLIT + split) * 4096;
#pragma unroll
    for (int i = 0; i < 4; i++) {
        float4 o = {acc[i][0], acc[i][1], acc[i][2], acc[i][3]};
        *(float4*)&kvdst[(te + i) * 64 + td] = o;
    }
    if (t < 64) g_ksp[((size_t)bh * KSPLIT + split) * 64 + t] = ksum_acc;
}

// ---------------------------------------------------------------------------
// Stage 3: out[s, h*64+d] = (q . kv) / (q . k_sum + eps).
// ---------------------------------------------------------------------------
__global__ __launch_bounds__(256)
void attn_out_kernel()
{
    __shared__ float skv[64][64];
    __shared__ float sks[64];
    __shared__ float sq[8][64];

    const int bh = blockIdx.x;
    const int b  = bh / 12;
    const int h  = bh - b * 12;
    const int t  = threadIdx.x;

    for (int idx = t; idx < 4096; idx += 256) {
        float sum = 0.f;
        const float* p = g_kvp + (size_t)bh * KSPLIT * 4096 + idx;
#pragma unroll
        for (int s = 0; s < KSPLIT; s++) sum += p[(size_t)s * 4096];
        skv[idx >> 6][idx & 63] = sum;
    }
    if (t < 64) {
        float sum = 0.f;
        const float* p = g_ksp + (size_t)bh * KSPLIT * 64 + t;
#pragma unroll
        for (int s = 0; s < KSPLIT; s++) sum += p[(size_t)s * 64];
        sks[t] = sum;
    }
    __syncthreads();

    const int w    = t >> 5;
    const int lane = t & 31;
    const int sBase = blockIdx.y * 196;

    for (int si = w; si < 196; si += 8) {
        const int s = sBase + si;
        const float* qrow = g_q + (size_t)(b * SLEN + s) * CDIM + h * 64;
        float2 q2 = *(const float2*)&qrow[lane * 2];
        sq[w][lane * 2]     = q2.x;
        sq[w][lane * 2 + 1] = q2.y;
        __syncwarp();

        float acc0 = 0.f, acc1 = 0.f, accz = 0.f;
#pragma unroll 8
        for (int e = 0; e < 64; e++) {
            const float qv = sq[w][e];
            acc0 += qv * skv[e][lane];
            acc1 += qv * skv[e][lane + 32];
            accz += qv * sks[e];
        }
        const float z = 1.f / (accz + 1e-4f);
        float* orow = g_att + (size_t)(b * SLEN + s) * CDIM + h * 64;
        orow[lane]      = acc0 * z;
        orow[lane + 32] = acc1 * z;
        __syncwarp();
    }
}

// ---------------------------------------------------------------------------

extern "C" void kernel_launch(void* const* d_in, const int* in_sizes, int n_in,
                              void* d_out, int out_size)
{
    const float* x     = (const float*)d_in[0];   // (128,196,768)
    const float* Wqkv  = (const float*)d_in[1];   // (2304,768)
    const float* Wproj = (const float*)d_in[2];   // (768,768)
    const float* bproj = (const float*)d_in[3];   // (768)
    float* out = (float*)d_out;

    mma_gemm_kernel <<<dim3(MTOK / 128, 2304 / 128), 256>>>(x, Wqkv, nullptr, nullptr, 0);
    kv_partial_kernel<<<dim3(NBH, KSPLIT),           256>>>();
    attn_out_kernel  <<<dim3(NBH, SLEN / 196),       256>>>();
    mma_gemm_kernel <<<dim3(MTOK / 128, CDIM / 128), 256>>>(nullptr, Wproj, bproj, out, 1);
}

// round 16
// speedup vs baseline: 1.4525x; 1.4525x over previous
#include <cuda_runtime.h>
#include <cstdint>

// ---------------------------------------------------------------------------
// LinearAttention: B=128, N=196, C=768, h=12, e=64, num_frames=16
//   b = 8, S = 3136, M = 25088 tokens.  (B,N)->(b,S) reshape is row-identity.
//
// Pre-pass: round x, W_qkv, W_proj to tf32-in-f32 (cvt.rna) ONCE.
//   -> GEMM mainloop is pure cp.async + LDS + mma.sync: the tensor core's
//      truncation of pre-rounded values is the identity, so no cvt anywhere
//      in the hot loop. Numerically identical to converting at fill (R13).
// Stage 1: qkv = x @ W_qkv^T          -> tf32 mma.sync, relu+scatter epi
// Stage 2: kv[b,h,e,d], k_sum[b,h,e]  -> fp32 SIMT split-K
// Stage 3: out = (q.kv)/(q.k_sum+eps) -> fp32 SIMT, writes g_att pre-rounded
// Stage 4: final = out @ W_proj^T + b -> tf32 mma.sync, bias epi
//
// R15 bug fixed here: g_att was passed as a host-side symbol to the proj
// GEMM (garbage pointer). All device-global operands now go through
// cudaGetSymbolAddress.
// ---------------------------------------------------------------------------

#define MTOK   25088
#define CDIM   768
#define SLEN   3136
#define NBH    96
#define KSPLIT 7
#define SCHUNK 448
#define NQKV   2304

__device__ float g_q  [(size_t)MTOK * CDIM];
__device__ float g_k  [(size_t)MTOK * CDIM];
__device__ float g_v  [(size_t)MTOK * CDIM];
__device__ float g_att[(size_t)MTOK * CDIM];
__device__ float g_kvp [NBH * KSPLIT * 64 * 64];
__device__ float g_ksp [NBH * KSPLIT * 64];
// pre-rounded (tf32-in-f32) operands
__device__ float g_xr [(size_t)MTOK * CDIM];
__device__ float g_wq [(size_t)NQKV * CDIM];
__device__ float g_wp [(size_t)CDIM * CDIM];

__device__ __forceinline__ uint32_t f32_to_tf32(float f) {
    uint32_t r;
    asm("cvt.rna.tf32.f32 %0, %1;" : "=r"(r) : "f"(f));
    return r;
}
__device__ __forceinline__ uint32_t smem_u32(const void* p) {
    uint32_t a;
    asm("{ .reg .u64 t; cvta.to.shared.u64 t, %1; cvt.u32.u64 %0, t; }"
        : "=r"(a) : "l"(p));
    return a;
}
__device__ __forceinline__ void cp_async16(uint32_t dst, const void* src) {
    asm volatile("cp.async.cg.shared.global [%0], [%1], 16;"
                 :: "r"(dst), "l"(src));
}
__device__ __forceinline__ void cp_commit() {
    asm volatile("cp.async.commit_group;" ::: "memory");
}
__device__ __forceinline__ void cp_wait1() {
    asm volatile("cp.async.wait_group 1;" ::: "memory");
}
__device__ __forceinline__ void cp_wait0() {
    asm volatile("cp.async.wait_group 0;" ::: "memory");
}

// D += A(16x8,row) x B(8x8,col) in tf32, f32 accum.
__device__ __forceinline__ void mma_tf32(float c[4],
                                         const uint32_t a[4],
                                         const uint32_t b[2])
{
    asm volatile(
        "mma.sync.aligned.m16n8k8.row.col.f32.tf32.tf32.f32 "
        "{%0,%1,%2,%3}, {%4,%5,%6,%7}, {%8,%9}, {%0,%1,%2,%3};\n"
        : "+f"(c[0]), "+f"(c[1]), "+f"(c[2]), "+f"(c[3])
        : "r"(a[0]), "r"(a[1]), "r"(a[2]), "r"(a[3]),
          "r"(b[0]), "r"(b[1]));
}

// ---------------------------------------------------------------------------
// Pre-pass: dst[i] = round_to_tf32(src[i]) (value kept in f32 format).
// ---------------------------------------------------------------------------
__global__ __launch_bounds__(256)
void round_tf32_kernel(const float* __restrict__ src, float* __restrict__ dst,
                       int n4)
{
    const int i = blockIdx.x * 256 + threadIdx.x;
    if (i >= n4) return;
    float4 v = ((const float4*)src)[i];
    float4 o = { __uint_as_float(f32_to_tf32(v.x)),
                 __uint_as_float(f32_to_tf32(v.y)),
                 __uint_as_float(f32_to_tf32(v.z)),
                 __uint_as_float(f32_to_tf32(v.w)) };
    ((float4*)dst)[i] = o;
}

// ---------------------------------------------------------------------------
// tf32 GEMM: C[128 x 128] tile of A(MxK,row) @ Bt(NxK,row)^T, K = 768.
// 256 thr = 8 warps (2 m x 4 n); warp = 64x32 via 4x4 m16n8k8 frags.
// 2-stage cp.async pipeline, KCHUNK=16, pitch 20 words (conflict-free LDS).
// Operands pre-rounded -> no cvt in the loop; MMA truncation is identity.
// mode 0: qkv epilogue (relu on q,k; scatter to g_q/g_k/g_v)
// mode 1: proj epilogue (+bias -> out)
// ---------------------------------------------------------------------------
#define KCHUNK 16
#define NCHUNK (CDIM / KCHUNK)   // 48
#define SPAD   20

__global__ __launch_bounds__(256, 2)
void mma_gemm_kernel(const float* __restrict__ A, const float* __restrict__ Bt,
                     const float* __restrict__ bias, float* __restrict__ out,
                     int mode)
{
    __shared__ uint32_t As[2][128][SPAD];   // [stage][m][k], 16 valid k cols
    __shared__ uint32_t Bs[2][128][SPAD];   // [stage][n][k]

    const int t     = threadIdx.x;
    const int mBase = blockIdx.x * 128;
    const int nBase = blockIdx.y * 128;

    const int wid  = t >> 5;
    const int lane = t & 31;
    const int g    = lane >> 2;          // group id 0..7
    const int tig  = lane & 3;           // thread-in-group
    const int wm   = (wid >> 2) * 64;    // warp m offset
    const int wn   = (wid & 3) * 32;     // warp n offset

    // fill mapping: 512 float4 per matrix per chunk; 2 per thread per matrix
    const int fr = t >> 2;               // row (+0 / +64)
    const int fk = (t & 3) * 4;          // k word offset

    const float* ArowP = A  + (size_t)(mBase + fr) * CDIM + fk;
    const float* BrowP = Bt + (size_t)(nBase + fr) * CDIM + fk;

    uint32_t sA[2][2], sB[2][2];
#pragma unroll
    for (int st = 0; st < 2; st++)
#pragma unroll
        for (int i = 0; i < 2; i++) {
            sA[st][i] = smem_u32(&As[st][fr + i * 64][fk]);
            sB[st][i] = smem_u32(&Bs[st][fr + i * 64][fk]);
        }

    float acc[4][4][4];
#pragma unroll
    for (int i = 0; i < 4; i++)
#pragma unroll
        for (int j = 0; j < 4; j++)
#pragma unroll
            for (int r = 0; r < 4; r++) acc[i][j][r] = 0.f;

    // prologue: issue chunk 0 into stage 0
#pragma unroll
    for (int i = 0; i < 2; i++) {
        cp_async16(sA[0][i], ArowP + (size_t)i * 64 * CDIM);
        cp_async16(sB[0][i], BrowP + (size_t)i * 64 * CDIM);
    }
    cp_commit();

    for (int c = 0; c < NCHUNK; ++c) {
        const int buf = c & 1;
        if (c + 1 < NCHUNK) {
            const int kOff = (c + 1) * KCHUNK;
            const int nb   = buf ^ 1;
#pragma unroll
            for (int i = 0; i < 2; i++) {
                cp_async16(sA[nb][i], ArowP + (size_t)i * 64 * CDIM + kOff);
                cp_async16(sB[nb][i], BrowP + (size_t)i * 64 * CDIM + kOff);
            }
            cp_commit();
            cp_wait1();                  // chunk c complete (1 group pending)
        } else {
            cp_wait0();
        }
        __syncthreads();

#pragma unroll
        for (int ks = 0; ks < 2; ks++) {
            const int k0 = ks * 8;
            uint32_t afr[4][4];
#pragma unroll
            for (int mt = 0; mt < 4; mt++) {
                const int r0 = wm + mt * 16 + g;
                afr[mt][0] = As[buf][r0]    [k0 + tig];
                afr[mt][1] = As[buf][r0 + 8][k0 + tig];
                afr[mt][2] = As[buf][r0]    [k0 + tig + 4];
                afr[mt][3] = As[buf][r0 + 8][k0 + tig + 4];
            }
            uint32_t bfr[4][2];
#pragma unroll
            for (int nt = 0; nt < 4; nt++) {
                const int rn = wn + nt * 8 + g;
                bfr[nt][0] = Bs[buf][rn][k0 + tig];
                bfr[nt][1] = Bs[buf][rn][k0 + tig + 4];
            }
#pragma unroll
            for (int mt = 0; mt < 4; mt++)
#pragma unroll
                for (int nt = 0; nt < 4; nt++)
                    mma_tf32(acc[mt][nt], afr[mt], bfr[nt]);
        }
        __syncthreads();                 // all reads done before refill
    }

    // Epilogue. 128-wide n-tiles never straddle the 768 boundary (768%128==0).
    if (mode == 0) {
        const int which = nBase / CDIM;            // 0=q 1=k 2=v
        float* dst = (which == 0) ? g_q : (which == 1) ? g_k : g_v;
        const int lcolBase = nBase - which * CDIM;
        const bool doRelu = (which < 2);
#pragma unroll
        for (int mt = 0; mt < 4; mt++) {
#pragma unroll
            for (int nt = 0; nt < 4; nt++) {
                const int row0 = mBase + wm + mt * 16 + g;
                const int col  = lcolBase + wn + nt * 8 + tig * 2;
                float2 v01 = { acc[mt][nt][0], acc[mt][nt][1] };
                float2 v23 = { acc[mt][nt][2], acc[mt][nt][3] };
                if (doRelu) {
                    v01.x = fmaxf(v01.x, 0.f); v01.y = fmaxf(v01.y, 0.f);
                    v23.x = fmaxf(v23.x, 0.f); v23.y = fmaxf(v23.y, 0.f);
                }
                *(float2*)&dst[(size_t)row0 * CDIM + col]       = v01;
                *(float2*)&dst[(size_t)(row0 + 8) * CDIM + col] = v23;
            }
        }
    } else {
#pragma unroll
        for (int mt = 0; mt < 4; mt++) {
#pragma unroll
            for (int nt = 0; nt < 4; nt++) {
                const int row0 = mBase + wm + mt * 16 + g;
                const int col  = nBase + wn + nt * 8 + tig * 2;
                const float2 b2 = *(const float2*)&bias[col];
                float2 v01 = { acc[mt][nt][0] + b2.x, acc[mt][nt][1] + b2.y };
                float2 v23 = { acc[mt][nt][2] + b2.x, acc[mt][nt][3] + b2.y };
                *(float2*)&out[(size_t)row0 * CDIM + col]       = v01;
                *(float2*)&out[(size_t)(row0 + 8) * CDIM + col] = v23;
            }
        }
    }
}

// ---------------------------------------------------------------------------
// Stage 2: per-(b,h) 64x64 kv = K^T V and k_sum, split-K over s (7 partials).
// ---------------------------------------------------------------------------
__global__ __launch_bounds__(256)
void kv_partial_kernel()
{
    __shared__ float ks[16][64];
    __shared__ float vs[16][64];

    const int bh    = blockIdx.x;
    const int b     = bh / 12;
    const int h     = bh - b * 12;
    const int split = blockIdx.y;
    const int s0    = split * SCHUNK;

    const int t  = threadIdx.x;
    const int te = (t & 15) << 2;
    const int td = (t >> 4) << 2;

    const float* kbase = g_k + (size_t)b * SLEN * CDIM + h * 64;
    const float* vbase = g_v + (size_t)b * SLEN * CDIM + h * 64;

    const int lrow = t >> 4;
    const int lc4  = t & 15;

    float acc[4][4];
#pragma unroll
    for (int i = 0; i < 4; i++)
#pragma unroll
        for (int j = 0; j < 4; j++) acc[i][j] = 0.f;
    float ksum_acc = 0.f;

    for (int c = 0; c < SCHUNK / 16; ++c) {
        const int s = s0 + c * 16;
        __syncthreads();
        ((float4*)ks[lrow])[lc4] =
            *(const float4*)&kbase[(size_t)(s + lrow) * CDIM + lc4 * 4];
        ((float4*)vs[lrow])[lc4] =
            *(const float4*)&vbase[(size_t)(s + lrow) * CDIM + lc4 * 4];
        __syncthreads();

        if (t < 64) {
#pragma unroll
            for (int ss = 0; ss < 16; ss++) ksum_acc += ks[ss][t];
        }
#pragma unroll
        for (int ss = 0; ss < 16; ss++) {
            float4 k4 = ((const float4*)ks[ss])[t & 15];
            float4 v4 = ((const float4*)vs[ss])[t >> 4];
            float kv_[4] = {k4.x, k4.y, k4.z, k4.w};
            float vv_[4] = {v4.x, v4.y, v4.z, v4.w};
#pragma unroll
            for (int i = 0; i < 4; i++)
#pragma unroll
                for (int j = 0; j < 4; j++) acc[i][j] += kv_[i] * vv_[j];
        }
    }

    float* kvdst = g_kvp + ((size_t)bh * KSPLIT + split) * 4096;
#pragma unroll
    for (int i = 0; i < 4; i++) {
        float4 o = {acc[i][0], acc[i][1], acc[i][2], acc[i][3]};
        *(float4*)&kvdst[(te + i) * 64 + td] = o;
    }
    if (t < 64) g_ksp[((size_t)bh * KSPLIT + split) * 64 + t] = ksum_acc;
}

// ---------------------------------------------------------------------------
// Stage 3: out[s, h*64+d] = (q . kv) / (q . k_sum + eps).
// Writes g_att pre-rounded to tf32 so the proj GEMM needs no conversion.
// ---------------------------------------------------------------------------
__global__ __launch_bounds__(256)
void attn_out_kernel()
{
    __shared__ float skv[64][64];
    __shared__ float sks[64];
    __shared__ float sq[8][64];

    const int bh = blockIdx.x;
    const int b  = bh / 12;
    const int h  = bh - b * 12;
    const int t  = threadIdx.x;

    for (int idx = t; idx < 4096; idx += 256) {
        float sum = 0.f;
        const float* p = g_kvp + (size_t)bh * KSPLIT * 4096 + idx;
#pragma unroll
        for (int s = 0; s < KSPLIT; s++) sum += p[(size_t)s * 4096];
        skv[idx >> 6][idx & 63] = sum;
    }
    if (t < 64) {
        float sum = 0.f;
        const float* p = g_ksp + (size_t)bh * KSPLIT * 64 + t;
#pragma unroll
        for (int s = 0; s < KSPLIT; s++) sum += p[(size_t)s * 64];
        sks[t] = sum;
    }
    __syncthreads();

    const int w    = t >> 5;
    const int lane = t & 31;
    const int sBase = blockIdx.y * 196;

    for (int si = w; si < 196; si += 8) {
        const int s = sBase + si;
        const float* qrow = g_q + (size_t)(b * SLEN + s) * CDIM + h * 64;
        float2 q2 = *(const float2*)&qrow[lane * 2];
        sq[w][lane * 2]     = q2.x;
        sq[w][lane * 2 + 1] = q2.y;
        __syncwarp();

        float acc0 = 0.f, acc1 = 0.f, accz = 0.f;
#pragma unroll 8
        for (int e = 0; e < 64; e++) {
            const float qv = sq[w][e];
            acc0 += qv * skv[e][lane];
            acc1 += qv * skv[e][lane + 32];
            accz += qv * sks[e];
        }
        const float z = 1.f / (accz + 1e-4f);
        float* orow = g_att + (size_t)(b * SLEN + s) * CDIM + h * 64;
        orow[lane]      = __uint_as_float(f32_to_tf32(acc0 * z));
        orow[lane + 32] = __uint_as_float(f32_to_tf32(acc1 * z));
        __syncwarp();
    }
}

// ---------------------------------------------------------------------------

extern "C" void kernel_launch(void* const* d_in, const int* in_sizes, int n_in,
                              void* d_out, int out_size)
{
    const float* x     = (const float*)d_in[0];   // (128,196,768)
    const float* Wqkv  = (const float*)d_in[1];   // (2304,768)
    const float* Wproj = (const float*)d_in[2];   // (768,768)
    const float* bproj = (const float*)d_in[3];   // (768)
    float* out = (float*)d_out;

    float* xr;  cudaGetSymbolAddress((void**)&xr,  g_xr);
    float* wq;  cudaGetSymbolAddress((void**)&wq,  g_wq);
    float* wp;  cudaGetSymbolAddress((void**)&wp,  g_wp);
    float* att; cudaGetSymbolAddress((void**)&att, g_att);   // R15 fix

    const int nx = MTOK * CDIM / 4, nq = NQKV * CDIM / 4, np = CDIM * CDIM / 4;
    round_tf32_kernel<<<(nx + 255) / 256, 256>>>(x,     xr, nx);
    round_tf32_kernel<<<(nq + 255) / 256, 256>>>(Wqkv,  wq, nq);
    round_tf32_kernel<<<(np + 255) / 256, 256>>>(Wproj, wp, np);

    mma_gemm_kernel <<<dim3(MTOK / 128, NQKV / 128), 256>>>(xr, wq, nullptr, nullptr, 0);
    kv_partial_kernel<<<dim3(NBH, KSPLIT),           256>>>();
    attn_out_kernel  <<<dim3(NBH, SLEN / 196),       256>>>();
    mma_gemm_kernel <<<dim3(MTOK / 128, CDIM / 128), 256>>>(att, wp, bproj, out, 1);
}